// round 9
// baseline (speedup 1.0000x reference)
#include <cuda_runtime.h>
#include <cuda_bf16.h>
#include <math.h>

#define QLEN   2048
#define HID    4096
#define NHEADS 32
#define ROWS   (NHEADS * QLEN)      // 65536
#define RPC    32                   // rows per chunk (contiguous 256KB stream)
#define NCHUNK (ROWS / RPC)         // 2048
#define ROWF4  (QLEN / 4)           // 512 float4 per row
#define SELB   64                   // select-kernel blocks (all co-resident)

// ---- scratch ----
__device__ float              g_partial[NCHUNK][QLEN];   // 16 MB
__device__ unsigned long long g_key[QLEN];
__device__ int                g_flag[QLEN];
__device__ int                g_keep[QLEN];
__device__ int                g_nkeep;
__device__ int                g_bar1, g_bar2;            // zero-init; reset each run

__device__ __forceinline__ unsigned long long dkey(double d) {
    unsigned long long u = __double_as_longlong(d);
    return (u & 0x8000000000000000ull) ? ~u : (u | 0x8000000000000000ull);
}

// K1: contiguous-streaming partial sums. grid = NCHUNK, block = 512. (proven ~6TB/s)
__global__ void k_partial(const float* __restrict__ w) {
    const int t = threadIdx.x;
    const float4* p = reinterpret_cast<const float4*>(w)
                    + (size_t)blockIdx.x * RPC * ROWF4 + t;
    float4 a0 = make_float4(0.f,0.f,0.f,0.f);
    float4 a1 = make_float4(0.f,0.f,0.f,0.f);
#pragma unroll
    for (int r = 0; r < RPC; r += 4) {
        float4 v0 = p[(size_t)(r + 0) * ROWF4];
        float4 v1 = p[(size_t)(r + 1) * ROWF4];
        float4 v2 = p[(size_t)(r + 2) * ROWF4];
        float4 v3 = p[(size_t)(r + 3) * ROWF4];
        a0.x += v0.x; a0.y += v0.y; a0.z += v0.z; a0.w += v0.w;
        a1.x += v1.x; a1.y += v1.y; a1.z += v1.z; a1.w += v1.w;
        a0.x += v2.x; a0.y += v2.y; a0.z += v2.z; a0.w += v2.w;
        a1.x += v3.x; a1.y += v3.y; a1.z += v3.z; a1.w += v3.w;
    }
    float4 s;
    s.x = a0.x + a1.x; s.y = a0.y + a1.y; s.z = a0.z + a1.z; s.w = a0.w + a1.w;
    *reinterpret_cast<float4*>(&g_partial[blockIdx.x][t * 4]) = s;
}

// software global barrier for the 64-block select kernel
__device__ __forceinline__ void gbar(int* ctr) {
    __syncthreads();
    if (threadIdx.x == 0) {
        __threadfence();
        atomicAdd(ctr, 1);
        while (atomicAdd(ctr, 0) < SELB) { }
        __threadfence();
    }
    __syncthreads();
}

// K2: fused finalize + rank + compact. grid = SELB (64), block = 256.
__global__ void k_select(const int* __restrict__ startp, const int* __restrict__ lenp) {
    __shared__ unsigned long long sk[QLEN];      // 16 KB
    __shared__ double sA[8][32];                 // 2 KB
    __shared__ int wsum[8];
    const int t = threadIdx.x;
    const int w = t >> 5, l = t & 31;
    const int b = blockIdx.x;

    // ---- Phase A: reduce 2048 chunk-partials -> keys for cols [b*32, b*32+32)
    const int col = b * 32 + l;
    {
        double a[8] = {0,0,0,0,0,0,0,0};
        for (int c = w * 8; c < NCHUNK; c += 64) {
#pragma unroll
            for (int q = 0; q < 8; ++q)
                a[q] += (double)g_partial[c + q][col];
        }
        sA[w][l] = ((a[0]+a[1]) + (a[2]+a[3])) + ((a[4]+a[5]) + (a[6]+a[7]));
        __syncthreads();
        if (w == 0) {
            double s = 0.0;
#pragma unroll
            for (int q = 0; q < 8; ++q) s += sA[q][l];
            g_key[col] = dkey(s);
        }
    }
    gbar(&g_bar1);

    // ---- Phase B: rank 32 positions per block against all image keys
    const int start = *startp;
    const int ilen  = *lenp;
    const int keep_k = (int)llrint((double)ilen * (1.0 - 0.3));
    for (int i = t; i < QLEN; i += 256) sk[i] = g_key[i];
    __syncthreads();

    {
        const int p0 = b * 32 + w * 4;
        unsigned long long v[4];
        int idx[4];
        bool img[4];
#pragma unroll
        for (int q = 0; q < 4; ++q) {
            const int p = p0 + q;
            img[q] = (p >= start) && (p < start + ilen);
            idx[q] = img[q] ? (p - start) : 0;
            v[q]   = sk[start + idx[q]];
        }
        int c0 = 0, c1 = 0, c2 = 0, c3 = 0;
        for (int j = l; j < ilen; j += 32) {
            const unsigned long long u = sk[start + j];
            c0 += (u > v[0]) || (u == v[0] && j < idx[0]);
            c1 += (u > v[1]) || (u == v[1] && j < idx[1]);
            c2 += (u > v[2]) || (u == v[2] && j < idx[2]);
            c3 += (u > v[3]) || (u == v[3] && j < idx[3]);
        }
        c0 = __reduce_add_sync(0xffffffffu, c0);
        c1 = __reduce_add_sync(0xffffffffu, c1);
        c2 = __reduce_add_sync(0xffffffffu, c2);
        c3 = __reduce_add_sync(0xffffffffu, c3);
        if (l == 0) {
            const int cc[4] = {c0, c1, c2, c3};
#pragma unroll
            for (int q = 0; q < 4; ++q)
                g_flag[p0 + q] = img[q] ? ((cc[q] < keep_k) ? 1 : 0) : 1;
        }
    }
    gbar(&g_bar2);

    // ---- Phase C: block 0 compacts; resets barrier counters for next replay
    if (b == 0) {
        int f[8];
        int cnt = 0;
        const int base0 = t * 8;
#pragma unroll
        for (int q = 0; q < 8; ++q) { f[q] = g_flag[base0 + q]; cnt += f[q]; }
        int v = cnt;
#pragma unroll
        for (int o = 1; o < 32; o <<= 1) {
            int n = __shfl_up_sync(0xffffffffu, v, o);
            if (l >= o) v += n;
        }
        if (l == 31) wsum[w] = v;
        __syncthreads();
        if (w == 0 && l < 8) {
            int x = wsum[l];
#pragma unroll
            for (int o = 1; o < 8; o <<= 1) {
                int n = __shfl_up_sync(0xffu, x, o);
                if (l >= o) x += n;
            }
            wsum[l] = x;
        }
        __syncthreads();
        int pos = (w ? wsum[w - 1] : 0) + v - cnt;
#pragma unroll
        for (int q = 0; q < 8; ++q) {
            if (f[q]) g_keep[pos++] = base0 + q;
        }
        if (t == 255) g_nkeep = wsum[7];
        if (t == 0) { g_bar1 = 0; g_bar2 = 0; }
    }
}

// K3: merged gather. grid = (QLEN, 3), block = 512. y=0 hs, y=1 pe, y=2 mask.
__global__ void k_gather(const float* __restrict__ hs,
                         const float* __restrict__ pe,
                         const float* __restrict__ mask,
                         float* __restrict__ out) {
    __shared__ float srow[QLEN];
    const int nk = g_nkeep;
    const int r = blockIdx.x;
    if (r >= nk) return;
    const int t = threadIdx.x;
    const int srcrow = g_keep[r];
    if (blockIdx.y < 2) {
        const float* sp = (blockIdx.y ? pe : hs) + (size_t)srcrow * HID;
        float* dp = out + (size_t)blockIdx.y * nk * HID + (size_t)r * HID;
        const float4* s4 = reinterpret_cast<const float4*>(sp);
        float4* d4 = reinterpret_cast<float4*>(dp);
#pragma unroll
        for (int i = t; i < HID / 4; i += 512) d4[i] = s4[i];
    } else {
        const float* mp = mask + (size_t)srcrow * QLEN;
#pragma unroll
        for (int i = t; i < QLEN; i += 512) srow[i] = mp[i];
        __syncthreads();
        const size_t base = 2ull * (size_t)nk * HID + (size_t)r * nk;
        for (int c = t; c < nk; c += 512)
            out[base + c] = srow[g_keep[c]];
    }
}

extern "C" void kernel_launch(void* const* d_in, const int* in_sizes, int n_in,
                              void* d_out, int out_size) {
    const float* hs   = (const float*)d_in[0];
    const float* pe   = (const float*)d_in[1];
    const float* mask = (const float*)d_in[2];
    const float* attn = (const float*)d_in[3];
    const int* startp = (const int*)d_in[4];
    const int* lenp   = (const int*)d_in[5];
    float* out = (float*)d_out;

    k_partial<<<NCHUNK, 512>>>(attn);
    k_select<<<SELB, 256>>>(startp, lenp);
    dim3 gg(QLEN, 3);
    k_gather<<<gg, 512>>>(hs, pe, mask, out);
}

// round 12
// speedup vs baseline: 1.0150x; 1.0150x over previous
#include <cuda_runtime.h>
#include <cuda_bf16.h>
#include <math.h>

#define QLEN   2048
#define HID    4096
#define NHEADS 32
#define ROWS   (NHEADS * QLEN)      // 65536
#define RPC    32                   // rows per chunk (contiguous 256KB stream)
#define NCHUNK (ROWS / RPC)         // 2048
#define ROWF4  (QLEN / 4)           // 512 float4 per row
#define NSLICE 32

// ---- scratch ----
__device__ float              g_partial[NCHUNK][QLEN];   // 16 MB
__device__ double             g_pd[NSLICE][QLEN];        // 512 KB
__device__ unsigned long long g_key[QLEN];
__device__ int                g_flag[QLEN];
__device__ int                g_keep[QLEN];
__device__ int                g_nkeep;
__device__ int                g_done_a, g_done_r;        // zero-init; reset by consumer

__device__ __forceinline__ unsigned long long dkey(double d) {
    unsigned long long u = __double_as_longlong(d);
    return (u & 0x8000000000000000ull) ? ~u : (u | 0x8000000000000000ull);
}

// K1: contiguous-streaming partial sums. grid = NCHUNK, block = 512.
// Measured: 80us, 87% DRAM, 6.9 TB/s. Do not touch.
__global__ void k_partial(const float* __restrict__ w) {
    const int t = threadIdx.x;
    const float4* p = reinterpret_cast<const float4*>(w)
                    + (size_t)blockIdx.x * RPC * ROWF4 + t;
    float4 a0 = make_float4(0.f,0.f,0.f,0.f);
    float4 a1 = make_float4(0.f,0.f,0.f,0.f);
#pragma unroll
    for (int r = 0; r < RPC; r += 4) {
        float4 v0 = p[(size_t)(r + 0) * ROWF4];
        float4 v1 = p[(size_t)(r + 1) * ROWF4];
        float4 v2 = p[(size_t)(r + 2) * ROWF4];
        float4 v3 = p[(size_t)(r + 3) * ROWF4];
        a0.x += v0.x; a0.y += v0.y; a0.z += v0.z; a0.w += v0.w;
        a1.x += v1.x; a1.y += v1.y; a1.z += v1.z; a1.w += v1.w;
        a0.x += v2.x; a0.y += v2.y; a0.z += v2.z; a0.w += v2.w;
        a1.x += v3.x; a1.y += v3.y; a1.z += v3.z; a1.w += v3.w;
    }
    float4 s;
    s.x = a0.x + a1.x; s.y = a0.y + a1.y; s.z = a0.z + a1.z; s.w = a0.w + a1.w;
    *reinterpret_cast<float4*>(&g_partial[blockIdx.x][t * 4]) = s;
}

// K2: finalize stage-a (R7 shape, 256 blocks coalesced) + last-block stage-b.
__global__ void k_finalize() {
    const int g = blockIdx.x * 256 + threadIdx.x;
    const int col = g & (QLEN - 1);
    const int sl  = g >> 11;
    const int c0  = sl * (NCHUNK / NSLICE);      // 64 chunks per slice
    double a[8] = {0,0,0,0,0,0,0,0};
#pragma unroll
    for (int c = 0; c < NCHUNK / NSLICE; c += 8) {
#pragma unroll
        for (int q = 0; q < 8; ++q) a[q] += (double)g_partial[c0 + c + q][col];
    }
    g_pd[sl][col] = ((a[0]+a[1]) + (a[2]+a[3])) + ((a[4]+a[5]) + (a[6]+a[7]));

    // last-block-done: the final block to finish runs stage-b inline.
    __shared__ int s_last;
    __threadfence();
    __syncthreads();
    if (threadIdx.x == 0)
        s_last = (atomicAdd(&g_done_a, 1) == gridDim.x - 1) ? 1 : 0;
    __syncthreads();
    if (!s_last) return;
    __threadfence();

    // stage-b: 256 threads, 8 cols each, reduce 32 slices in double.
    for (int cc = threadIdx.x; cc < QLEN; cc += 256) {
        double b[8] = {0,0,0,0,0,0,0,0};
#pragma unroll
        for (int s = 0; s < NSLICE; s += 8) {
#pragma unroll
            for (int q = 0; q < 8; ++q) b[q] += g_pd[s + q][cc];
        }
        g_key[cc] = dkey(((b[0]+b[1]) + (b[2]+b[3])) + ((b[4]+b[5]) + (b[6]+b[7])));
    }
    if (threadIdx.x == 0) g_done_a = 0;          // reset for next graph replay
}

// K3: rank (R7 shape: 256 blocks, warp per position) + last-block compact.
__global__ void k_rank(const int* __restrict__ startp, const int* __restrict__ lenp) {
    __shared__ unsigned long long sk[QLEN];
    const int start = *startp;
    const int ilen  = *lenp;
    const int t = threadIdx.x;
    for (int i = t; i < ilen; i += 256) sk[i] = g_key[start + i];
    __syncthreads();
    const int w = t >> 5, lane = t & 31;
    const int p = blockIdx.x * 8 + w;
    const int keep_k = (int)llrint((double)ilen * (1.0 - 0.3));
    if (p < start || p >= start + ilen) {
        if (lane == 0) g_flag[p] = 1;
    } else {
        const int i = p - start;
        const unsigned long long v = sk[i];
        int c = 0;
        for (int j = lane; j < ilen; j += 32) {
            const unsigned long long u = sk[j];
            c += (u > v) || (u == v && j < i);
        }
        c = __reduce_add_sync(0xffffffffu, c);
        if (lane == 0) g_flag[p] = (c < keep_k) ? 1 : 0;
    }

    // last-block-done: final block runs the compaction.
    __shared__ int s_last;
    __threadfence();
    __syncthreads();
    if (t == 0)
        s_last = (atomicAdd(&g_done_r, 1) == gridDim.x - 1) ? 1 : 0;
    __syncthreads();
    if (!s_last) return;
    __threadfence();

    // compact: 256 threads, 8 flags each, warp-scan of per-thread counts.
    __shared__ int wsum[8];
    int f[8];
    int cnt = 0;
    const int base0 = t * 8;
#pragma unroll
    for (int q = 0; q < 8; ++q) { f[q] = g_flag[base0 + q]; cnt += f[q]; }
    int v = cnt;
#pragma unroll
    for (int o = 1; o < 32; o <<= 1) {
        int n = __shfl_up_sync(0xffffffffu, v, o);
        if (lane >= o) v += n;
    }
    if (lane == 31) wsum[w] = v;
    __syncthreads();
    if (w == 0 && lane < 8) {
        int x = wsum[lane];
#pragma unroll
        for (int o = 1; o < 8; o <<= 1) {
            int n = __shfl_up_sync(0xffu, x, o);
            if (lane >= o) x += n;
        }
        wsum[lane] = x;
    }
    __syncthreads();
    int pos = (w ? wsum[w - 1] : 0) + v - cnt;
#pragma unroll
    for (int q = 0; q < 8; ++q) {
        if (f[q]) g_keep[pos++] = base0 + q;
    }
    if (t == 255) g_nkeep = wsum[7];
    if (t == 0) g_done_r = 0;                    // reset for next graph replay
}

// K4: merged gather. grid = (QLEN, 3), block = 512. y=0 hs, y=1 pe, y=2 mask.
__global__ void k_gather(const float* __restrict__ hs,
                         const float* __restrict__ pe,
                         const float* __restrict__ mask,
                         float* __restrict__ out) {
    __shared__ float srow[QLEN];
    const int nk = g_nkeep;
    const int r = blockIdx.x;
    if (r >= nk) return;
    const int t = threadIdx.x;
    const int srcrow = g_keep[r];
    if (blockIdx.y < 2) {
        const float* sp = (blockIdx.y ? pe : hs) + (size_t)srcrow * HID;
        float* dp = out + (size_t)blockIdx.y * nk * HID + (size_t)r * HID;
        const float4* s4 = reinterpret_cast<const float4*>(sp);
        float4* d4 = reinterpret_cast<float4*>(dp);
#pragma unroll
        for (int i = t; i < HID / 4; i += 512) d4[i] = s4[i];
    } else {
        const float* mp = mask + (size_t)srcrow * QLEN;
#pragma unroll
        for (int i = t; i < QLEN; i += 512) srow[i] = mp[i];
        __syncthreads();
        const size_t base = 2ull * (size_t)nk * HID + (size_t)r * nk;
        for (int c = t; c < nk; c += 512)
            out[base + c] = srow[g_keep[c]];
    }
}

extern "C" void kernel_launch(void* const* d_in, const int* in_sizes, int n_in,
                              void* d_out, int out_size) {
    const float* hs   = (const float*)d_in[0];
    const float* pe   = (const float*)d_in[1];
    const float* mask = (const float*)d_in[2];
    const float* attn = (const float*)d_in[3];
    const int* startp = (const int*)d_in[4];
    const int* lenp   = (const int*)d_in[5];
    float* out = (float*)d_out;

    k_partial<<<NCHUNK, 512>>>(attn);
    k_finalize<<<256, 256>>>();
    k_rank<<<QLEN / 8, 256>>>(startp, lenp);
    dim3 gg(QLEN, 3);
    k_gather<<<gg, 512>>>(hs, pe, mask, out);
}

// round 14
// speedup vs baseline: 1.1227x; 1.1060x over previous
#include <cuda_runtime.h>
#include <cuda_bf16.h>
#include <math.h>

#define QLEN   2048
#define HID    4096
#define NHEADS 32
#define ROWS   (NHEADS * QLEN)      // 65536
#define RPC    32                   // rows per chunk (contiguous 256KB stream)
#define NCHUNK (ROWS / RPC)         // 2048
#define ROWF4  (QLEN / 4)           // 512 float4 per row
#define NSLICE 32

// ---- scratch ----
__device__ float              g_partial[NCHUNK][QLEN];   // 16 MB
__device__ double             g_pd[NSLICE][QLEN];        // 512 KB
__device__ unsigned long long g_key[QLEN];
__device__ int                g_flag[QLEN];
__device__ int                g_keep[QLEN];
__device__ int                g_nkeep;

__device__ __forceinline__ unsigned long long dkey(double d) {
    unsigned long long u = __double_as_longlong(d);
    return (u & 0x8000000000000000ull) ? ~u : (u | 0x8000000000000000ull);
}

// K1: contiguous-streaming partial sums. grid = NCHUNK, block = 512.
// Measured: 80us, 87% DRAM, 6.9 TB/s. Frozen.
__global__ void k_partial(const float* __restrict__ w) {
    const int t = threadIdx.x;
    const float4* p = reinterpret_cast<const float4*>(w)
                    + (size_t)blockIdx.x * RPC * ROWF4 + t;
    float4 a0 = make_float4(0.f,0.f,0.f,0.f);
    float4 a1 = make_float4(0.f,0.f,0.f,0.f);
#pragma unroll
    for (int r = 0; r < RPC; r += 4) {
        float4 v0 = p[(size_t)(r + 0) * ROWF4];
        float4 v1 = p[(size_t)(r + 1) * ROWF4];
        float4 v2 = p[(size_t)(r + 2) * ROWF4];
        float4 v3 = p[(size_t)(r + 3) * ROWF4];
        a0.x += v0.x; a0.y += v0.y; a0.z += v0.z; a0.w += v0.w;
        a1.x += v1.x; a1.y += v1.y; a1.z += v1.z; a1.w += v1.w;
        a0.x += v2.x; a0.y += v2.y; a0.z += v2.z; a0.w += v2.w;
        a1.x += v3.x; a1.y += v3.y; a1.z += v3.z; a1.w += v3.w;
    }
    float4 s;
    s.x = a0.x + a1.x; s.y = a0.y + a1.y; s.z = a0.z + a1.z; s.w = a0.w + a1.w;
    *reinterpret_cast<float4*>(&g_partial[blockIdx.x][t * 4]) = s;
}

// K1b-a: 2048 chunk-partials -> 32 slice-partials (double). grid=256, block=256.
__global__ void k_finalize_a() {
    const int g = blockIdx.x * 256 + threadIdx.x;
    const int col = g & (QLEN - 1);
    const int sl  = g >> 11;
    const int c0  = sl * (NCHUNK / NSLICE);
    double a[8] = {0,0,0,0,0,0,0,0};
#pragma unroll
    for (int c = 0; c < NCHUNK / NSLICE; c += 8) {
#pragma unroll
        for (int q = 0; q < 8; ++q) a[q] += (double)g_partial[c0 + c + q][col];
    }
    g_pd[sl][col] = ((a[0]+a[1]) + (a[2]+a[3])) + ((a[4]+a[5]) + (a[6]+a[7]));
}

// K1b-b: 32 slice-partials -> key. grid=8, block=256.
__global__ void k_finalize_b() {
    const int col = blockIdx.x * 256 + threadIdx.x;
    double a[8] = {0,0,0,0,0,0,0,0};
#pragma unroll
    for (int s = 0; s < NSLICE; s += 8) {
#pragma unroll
        for (int q = 0; q < 8; ++q) a[q] += g_pd[s + q][col];
    }
    double s = ((a[0]+a[1]) + (a[2]+a[3])) + ((a[4]+a[5]) + (a[6]+a[7]));
    g_key[col] = dkey(s);
}

// K2a: rank counting (R7 shape, measured 8.0us). grid = QLEN/8, block = 256.
__global__ void k_rank(const int* __restrict__ startp, const int* __restrict__ lenp) {
    __shared__ unsigned long long sk[QLEN];
    const int start = *startp;
    const int ilen  = *lenp;
    const int t = threadIdx.x;
    for (int i = t; i < ilen; i += 256) sk[i] = g_key[start + i];
    __syncthreads();
    const int w = t >> 5, lane = t & 31;
    const int p = blockIdx.x * 8 + w;
    if (p >= QLEN) return;
    if (p < start || p >= start + ilen) {
        if (lane == 0) g_flag[p] = 1;
        return;
    }
    const int keep_k = (int)llrint((double)ilen * (1.0 - 0.3));
    const int i = p - start;
    const unsigned long long v = sk[i];
    int c = 0;
    for (int j = lane; j < ilen; j += 32) {
        const unsigned long long u = sk[j];
        c += (u > v) || (u == v && j < i);
    }
    c = __reduce_add_sync(0xffffffffu, c);
    if (lane == 0) g_flag[p] = (c < keep_k) ? 1 : 0;
}

// K2b: compact via ballot/popc. single block, 1024 threads, 2 elems/thread.
__global__ void k_compact() {
    const int t = threadIdx.x;
    const int lane = t & 31, w = t >> 5;
    const int f0 = g_flag[2 * t];
    const int f1 = g_flag[2 * t + 1];
    const unsigned b0 = __ballot_sync(0xffffffffu, f0);
    const unsigned b1 = __ballot_sync(0xffffffffu, f1);
    const unsigned lt = (1u << lane) - 1u;
    const int wtotal = __popc(b0) + __popc(b1);
    __shared__ int wsum[32];
    if (lane == 0) wsum[w] = wtotal;
    __syncthreads();
    if (w == 0) {
        int x = wsum[lane];
#pragma unroll
        for (int o = 1; o < 32; o <<= 1) {
            int n = __shfl_up_sync(0xffffffffu, x, o);
            if (lane >= o) x += n;
        }
        wsum[lane] = x;
    }
    __syncthreads();
    const int base = (w ? wsum[w - 1] : 0) + __popc(b0 & lt) + __popc(b1 & lt);
    if (f0) g_keep[base] = 2 * t;
    if (f1) g_keep[base + f0] = 2 * t + 1;
    if (t == 1023) g_nkeep = wsum[31];
}

// K3: gather hs / pe rows (R7 shape, measured 6.1 TB/s). grid=(QLEN,2), block=256.
__global__ void k_gather_rows(const float* __restrict__ hs,
                              const float* __restrict__ pe,
                              float* __restrict__ out) {
    const int nk = g_nkeep;
    const int r  = blockIdx.x;
    if (r >= nk) return;
    const int srcrow = g_keep[r];
    const float* sp = (blockIdx.y ? pe : hs) + (size_t)srcrow * HID;
    float* dp = out + (size_t)blockIdx.y * nk * HID + (size_t)r * HID;
    const float4* s4 = reinterpret_cast<const float4*>(sp);
    float4* d4 = reinterpret_cast<float4*>(dp);
#pragma unroll 4
    for (int i = threadIdx.x; i < HID / 4; i += 256) d4[i] = s4[i];
}

// K4: mask gather, direct gmem (no smem staging). grid = QLEN, block = 256.
__global__ void k_gather_mask(const float* __restrict__ mask,
                              float* __restrict__ out) {
    const int nk = g_nkeep;
    const int r = blockIdx.x;
    if (r >= nk) return;
    const int t = threadIdx.x;
    const float* mp = mask + (size_t)g_keep[r] * QLEN;
    const size_t base = 2ull * (size_t)nk * HID + (size_t)r * nk;
    for (int c = t; c < nk; c += 256)
        out[base + c] = __ldg(mp + g_keep[c]);
}

extern "C" void kernel_launch(void* const* d_in, const int* in_sizes, int n_in,
                              void* d_out, int out_size) {
    const float* hs   = (const float*)d_in[0];
    const float* pe   = (const float*)d_in[1];
    const float* mask = (const float*)d_in[2];
    const float* attn = (const float*)d_in[3];
    const int* startp = (const int*)d_in[4];
    const int* lenp   = (const int*)d_in[5];
    float* out = (float*)d_out;

    k_partial<<<NCHUNK, 512>>>(attn);
    k_finalize_a<<<256, 256>>>();
    k_finalize_b<<<8, 256>>>();
    k_rank<<<QLEN / 8, 256>>>(startp, lenp);
    k_compact<<<1, 1024>>>();
    dim3 g3(QLEN, 2);
    k_gather_rows<<<g3, 256>>>(hs, pe, out);
    k_gather_mask<<<QLEN, 256>>>(mask, out);
}

// round 16
// speedup vs baseline: 1.2495x; 1.1130x over previous
#include <cuda_runtime.h>
#include <cuda_bf16.h>
#include <math.h>

#define QLEN   2048
#define HID    4096
#define NHEADS 32
#define ROWS   (NHEADS * QLEN)      // 65536
#define RPC    64                   // rows per chunk (contiguous 512KB stream)
#define NCHUNK (ROWS / RPC)         // 1024
#define ROWF4  (QLEN / 4)           // 512 float4 per row
#define NSLICE 32                   // finalize slices (32 chunks each)

// ---- scratch ----
__device__ float              g_partial[NCHUNK][QLEN];   // 8 MB
__device__ double             g_pd[NSLICE][QLEN];        // 512 KB
__device__ unsigned long long g_key[QLEN];
__device__ int                g_flag[QLEN];
__device__ int                g_keep[QLEN];
__device__ int                g_nkeep;

__device__ __forceinline__ unsigned long long dkey(double d) {
    unsigned long long u = __double_as_longlong(d);
    return (u & 0x8000000000000000ull) ? ~u : (u | 0x8000000000000000ull);
}

// K1: contiguous-streaming partial sums. grid = NCHUNK (1024), block = 512.
// Same proven pattern as the measured 6.9 TB/s kernel; RPC doubled to halve
// partial traffic.
__global__ void k_partial(const float* __restrict__ w) {
    const int t = threadIdx.x;
    const float4* p = reinterpret_cast<const float4*>(w)
                    + (size_t)blockIdx.x * RPC * ROWF4 + t;
    float4 a0 = make_float4(0.f,0.f,0.f,0.f);
    float4 a1 = make_float4(0.f,0.f,0.f,0.f);
#pragma unroll
    for (int r = 0; r < RPC; r += 4) {
        float4 v0 = p[(size_t)(r + 0) * ROWF4];
        float4 v1 = p[(size_t)(r + 1) * ROWF4];
        float4 v2 = p[(size_t)(r + 2) * ROWF4];
        float4 v3 = p[(size_t)(r + 3) * ROWF4];
        a0.x += v0.x; a0.y += v0.y; a0.z += v0.z; a0.w += v0.w;
        a1.x += v1.x; a1.y += v1.y; a1.z += v1.z; a1.w += v1.w;
        a0.x += v2.x; a0.y += v2.y; a0.z += v2.z; a0.w += v2.w;
        a1.x += v3.x; a1.y += v3.y; a1.z += v3.z; a1.w += v3.w;
    }
    float4 s;
    s.x = a0.x + a1.x; s.y = a0.y + a1.y; s.z = a0.z + a1.z; s.w = a0.w + a1.w;
    *reinterpret_cast<float4*>(&g_partial[blockIdx.x][t * 4]) = s;
}

// K1b-a: 1024 chunk-partials -> 32 slice-partials (double). grid=256, block=256.
// 65536 threads: col = g & 2047, slice = g >> 11; 32 chunks per slice.
__global__ void k_finalize_a() {
    const int g = blockIdx.x * 256 + threadIdx.x;
    const int col = g & (QLEN - 1);
    const int sl  = g >> 11;
    const int c0  = sl * (NCHUNK / NSLICE);
    double a[8] = {0,0,0,0,0,0,0,0};
#pragma unroll
    for (int c = 0; c < NCHUNK / NSLICE; c += 8) {
#pragma unroll
        for (int q = 0; q < 8; ++q) a[q] += (double)g_partial[c0 + c + q][col];
    }
    g_pd[sl][col] = ((a[0]+a[1]) + (a[2]+a[3])) + ((a[4]+a[5]) + (a[6]+a[7]));
}

// K1b-b: 32 slice-partials -> key. grid=8, block=256.
__global__ void k_finalize_b() {
    const int col = blockIdx.x * 256 + threadIdx.x;
    double a[8] = {0,0,0,0,0,0,0,0};
#pragma unroll
    for (int s = 0; s < NSLICE; s += 8) {
#pragma unroll
        for (int q = 0; q < 8; ++q) a[q] += g_pd[s + q][col];
    }
    double s = ((a[0]+a[1]) + (a[2]+a[3])) + ((a[4]+a[5]) + (a[6]+a[7]));
    g_key[col] = dkey(s);
}

// K2a: rank counting (R7 shape, measured 8.0us). grid = QLEN/8, block = 256.
__global__ void k_rank(const int* __restrict__ startp, const int* __restrict__ lenp) {
    __shared__ unsigned long long sk[QLEN];
    const int start = *startp;
    const int ilen  = *lenp;
    const int t = threadIdx.x;
    for (int i = t; i < ilen; i += 256) sk[i] = g_key[start + i];
    __syncthreads();
    const int w = t >> 5, lane = t & 31;
    const int p = blockIdx.x * 8 + w;
    if (p >= QLEN) return;
    if (p < start || p >= start + ilen) {
        if (lane == 0) g_flag[p] = 1;
        return;
    }
    const int keep_k = (int)llrint((double)ilen * (1.0 - 0.3));
    const int i = p - start;
    const unsigned long long v = sk[i];
    int c = 0;
    for (int j = lane; j < ilen; j += 32) {
        const unsigned long long u = sk[j];
        c += (u > v) || (u == v && j < i);
    }
    c = __reduce_add_sync(0xffffffffu, c);
    if (lane == 0) g_flag[p] = (c < keep_k) ? 1 : 0;
}

// K2b: compact via ballot/popc. single block, 1024 threads, 2 elems/thread.
__global__ void k_compact() {
    const int t = threadIdx.x;
    const int lane = t & 31, w = t >> 5;
    const int f0 = g_flag[2 * t];
    const int f1 = g_flag[2 * t + 1];
    const unsigned b0 = __ballot_sync(0xffffffffu, f0);
    const unsigned b1 = __ballot_sync(0xffffffffu, f1);
    const unsigned lt = (1u << lane) - 1u;
    const int wtotal = __popc(b0) + __popc(b1);
    __shared__ int wsum[32];
    if (lane == 0) wsum[w] = wtotal;
    __syncthreads();
    if (w == 0) {
        int x = wsum[lane];
#pragma unroll
        for (int o = 1; o < 32; o <<= 1) {
            int n = __shfl_up_sync(0xffffffffu, x, o);
            if (lane >= o) x += n;
        }
        wsum[lane] = x;
    }
    __syncthreads();
    const int base = (w ? wsum[w - 1] : 0) + __popc(b0 & lt) + __popc(b1 & lt);
    if (f0) g_keep[base] = 2 * t;
    if (f1) g_keep[base + f0] = 2 * t + 1;
    if (t == 1023) g_nkeep = wsum[31];
}

// K3: merged gather (R7 shape, measured 21.3us). grid = (QLEN, 3), block = 512.
__global__ void k_gather(const float* __restrict__ hs,
                         const float* __restrict__ pe,
                         const float* __restrict__ mask,
                         float* __restrict__ out) {
    __shared__ float srow[QLEN];
    const int nk = g_nkeep;
    const int r = blockIdx.x;
    if (r >= nk) return;
    const int t = threadIdx.x;
    const int srcrow = g_keep[r];
    if (blockIdx.y < 2) {
        const float* sp = (blockIdx.y ? pe : hs) + (size_t)srcrow * HID;
        float* dp = out + (size_t)blockIdx.y * nk * HID + (size_t)r * HID;
        const float4* s4 = reinterpret_cast<const float4*>(sp);
        float4* d4 = reinterpret_cast<float4*>(dp);
#pragma unroll
        for (int i = t; i < HID / 4; i += 512) d4[i] = s4[i];
    } else {
        const float* mp = mask + (size_t)srcrow * QLEN;
#pragma unroll
        for (int i = t; i < QLEN; i += 512) srow[i] = mp[i];
        __syncthreads();
        const size_t base = 2ull * (size_t)nk * HID + (size_t)r * nk;
        for (int c = t; c < nk; c += 512)
            out[base + c] = srow[g_keep[c]];
    }
}

extern "C" void kernel_launch(void* const* d_in, const int* in_sizes, int n_in,
                              void* d_out, int out_size) {
    const float* hs   = (const float*)d_in[0];
    const float* pe   = (const float*)d_in[1];
    const float* mask = (const float*)d_in[2];
    const float* attn = (const float*)d_in[3];
    const int* startp = (const int*)d_in[4];
    const int* lenp   = (const int*)d_in[5];
    float* out = (float*)d_out;

    k_partial<<<NCHUNK, 512>>>(attn);
    k_finalize_a<<<256, 256>>>();
    k_finalize_b<<<8, 256>>>();
    k_rank<<<QLEN / 8, 256>>>(startp, lenp);
    k_compact<<<1, 1024>>>();
    dim3 gg(QLEN, 3);
    k_gather<<<gg, 512>>>(hs, pe, mask, out);
}

// round 17
// speedup vs baseline: 1.2815x; 1.0256x over previous
#include <cuda_runtime.h>
#include <cuda_bf16.h>
#include <math.h>

#define QLEN   2048
#define HID    4096
#define NHEADS 32
#define ROWS   (NHEADS * QLEN)      // 65536
#define RPC    128                  // rows per chunk (contiguous 1MB stream)
#define NCHUNK (ROWS / RPC)         // 512
#define ROWF4  (QLEN / 4)           // 512 float4 per row
#define NSLICE 32                   // finalize slices (16 chunks each)

// ---- scratch ----
__device__ float              g_partial[NCHUNK][QLEN];   // 4 MB
__device__ double             g_pd[NSLICE][QLEN];        // 512 KB
__device__ unsigned long long g_key[QLEN];
__device__ int                g_flag[QLEN];
__device__ int                g_keep[QLEN];
__device__ int                g_nkeep;

__device__ __forceinline__ unsigned long long dkey(double d) {
    unsigned long long u = __double_as_longlong(d);
    return (u & 0x8000000000000000ull) ? ~u : (u | 0x8000000000000000ull);
}

// K1: contiguous-streaming partial sums. grid = NCHUNK (512), block = 512.
// Proven 6.9 TB/s pattern; RPC=128 halves partial traffic vs R16.
__global__ void k_partial(const float* __restrict__ w) {
    const int t = threadIdx.x;
    const float4* p = reinterpret_cast<const float4*>(w)
                    + (size_t)blockIdx.x * RPC * ROWF4 + t;
    float4 a0 = make_float4(0.f,0.f,0.f,0.f);
    float4 a1 = make_float4(0.f,0.f,0.f,0.f);
#pragma unroll
    for (int r = 0; r < RPC; r += 4) {
        float4 v0 = p[(size_t)(r + 0) * ROWF4];
        float4 v1 = p[(size_t)(r + 1) * ROWF4];
        float4 v2 = p[(size_t)(r + 2) * ROWF4];
        float4 v3 = p[(size_t)(r + 3) * ROWF4];
        a0.x += v0.x; a0.y += v0.y; a0.z += v0.z; a0.w += v0.w;
        a1.x += v1.x; a1.y += v1.y; a1.z += v1.z; a1.w += v1.w;
        a0.x += v2.x; a0.y += v2.y; a0.z += v2.z; a0.w += v2.w;
        a1.x += v3.x; a1.y += v3.y; a1.z += v3.z; a1.w += v3.w;
    }
    float4 s;
    s.x = a0.x + a1.x; s.y = a0.y + a1.y; s.z = a0.z + a1.z; s.w = a0.w + a1.w;
    *reinterpret_cast<float4*>(&g_partial[blockIdx.x][t * 4]) = s;
}

// K1b-a: 512 chunk-partials -> 32 slice-partials (double). grid=256, block=256.
// 65536 threads: col = g & 2047, slice = g >> 11; 16 chunks per slice.
__global__ void k_finalize_a() {
    const int g = blockIdx.x * 256 + threadIdx.x;
    const int col = g & (QLEN - 1);
    const int sl  = g >> 11;
    const int c0  = sl * (NCHUNK / NSLICE);
    double a[8] = {0,0,0,0,0,0,0,0};
#pragma unroll
    for (int c = 0; c < NCHUNK / NSLICE; c += 8) {
#pragma unroll
        for (int q = 0; q < 8; ++q) a[q] += (double)g_partial[c0 + c + q][col];
    }
    g_pd[sl][col] = ((a[0]+a[1]) + (a[2]+a[3])) + ((a[4]+a[5]) + (a[6]+a[7]));
}

// K1b-b: 32 slice-partials -> key. grid=8, block=256.
__global__ void k_finalize_b() {
    const int col = blockIdx.x * 256 + threadIdx.x;
    double a[8] = {0,0,0,0,0,0,0,0};
#pragma unroll
    for (int s = 0; s < NSLICE; s += 8) {
#pragma unroll
        for (int q = 0; q < 8; ++q) a[q] += g_pd[s + q][col];
    }
    double s = ((a[0]+a[1]) + (a[2]+a[3])) + ((a[4]+a[5]) + (a[6]+a[7]));
    g_key[col] = dkey(s);
}

// K2a: rank counting. grid = QLEN/16 = 128 blocks, block = 512 (16 warps).
// One position per warp (inner loop identical to the measured 7.8us version);
// same total warp count (2048), half the staging instances.
__global__ void k_rank(const int* __restrict__ startp, const int* __restrict__ lenp) {
    __shared__ unsigned long long sk[QLEN];
    const int start = *startp;
    const int ilen  = *lenp;
    const int t = threadIdx.x;
    for (int i = t; i < ilen; i += 512) sk[i] = g_key[start + i];
    __syncthreads();
    const int w = t >> 5, lane = t & 31;
    const int p = blockIdx.x * 16 + w;
    if (p >= QLEN) return;
    if (p < start || p >= start + ilen) {
        if (lane == 0) g_flag[p] = 1;
        return;
    }
    const int keep_k = (int)llrint((double)ilen * (1.0 - 0.3));
    const int i = p - start;
    const unsigned long long v = sk[i];
    int c = 0;
    for (int j = lane; j < ilen; j += 32) {
        const unsigned long long u = sk[j];
        c += (u > v) || (u == v && j < i);
    }
    c = __reduce_add_sync(0xffffffffu, c);
    if (lane == 0) g_flag[p] = (c < keep_k) ? 1 : 0;
}

// K2b: compact via ballot/popc. single block, 1024 threads, 2 elems/thread.
__global__ void k_compact() {
    const int t = threadIdx.x;
    const int lane = t & 31, w = t >> 5;
    const int f0 = g_flag[2 * t];
    const int f1 = g_flag[2 * t + 1];
    const unsigned b0 = __ballot_sync(0xffffffffu, f0);
    const unsigned b1 = __ballot_sync(0xffffffffu, f1);
    const unsigned lt = (1u << lane) - 1u;
    const int wtotal = __popc(b0) + __popc(b1);
    __shared__ int wsum[32];
    if (lane == 0) wsum[w] = wtotal;
    __syncthreads();
    if (w == 0) {
        int x = wsum[lane];
#pragma unroll
        for (int o = 1; o < 32; o <<= 1) {
            int n = __shfl_up_sync(0xffffffffu, x, o);
            if (lane >= o) x += n;
        }
        wsum[lane] = x;
    }
    __syncthreads();
    const int base = (w ? wsum[w - 1] : 0) + __popc(b0 & lt) + __popc(b1 & lt);
    if (f0) g_keep[base] = 2 * t;
    if (f1) g_keep[base + f0] = 2 * t + 1;
    if (t == 1023) g_nkeep = wsum[31];
}

// K3: merged gather (frozen R16 shape). grid = (QLEN, 3), block = 512.
__global__ void k_gather(const float* __restrict__ hs,
                         const float* __restrict__ pe,
                         const float* __restrict__ mask,
                         float* __restrict__ out) {
    __shared__ float srow[QLEN];
    const int nk = g_nkeep;
    const int r = blockIdx.x;
    if (r >= nk) return;
    const int t = threadIdx.x;
    const int srcrow = g_keep[r];
    if (blockIdx.y < 2) {
        const float* sp = (blockIdx.y ? pe : hs) + (size_t)srcrow * HID;
        float* dp = out + (size_t)blockIdx.y * nk * HID + (size_t)r * HID;
        const float4* s4 = reinterpret_cast<const float4*>(sp);
        float4* d4 = reinterpret_cast<float4*>(dp);
#pragma unroll
        for (int i = t; i < HID / 4; i += 512) d4[i] = s4[i];
    } else {
        const float* mp = mask + (size_t)srcrow * QLEN;
#pragma unroll
        for (int i = t; i < QLEN; i += 512) srow[i] = mp[i];
        __syncthreads();
        const size_t base = 2ull * (size_t)nk * HID + (size_t)r * nk;
        for (int c = t; c < nk; c += 512)
            out[base + c] = srow[g_keep[c]];
    }
}

extern "C" void kernel_launch(void* const* d_in, const int* in_sizes, int n_in,
                              void* d_out, int out_size) {
    const float* hs   = (const float*)d_in[0];
    const float* pe   = (const float*)d_in[1];
    const float* mask = (const float*)d_in[2];
    const float* attn = (const float*)d_in[3];
    const int* startp = (const int*)d_in[4];
    const int* lenp   = (const int*)d_in[5];
    float* out = (float*)d_out;

    k_partial<<<NCHUNK, 512>>>(attn);
    k_finalize_a<<<256, 256>>>();
    k_finalize_b<<<8, 256>>>();
    k_rank<<<QLEN / 16, 512>>>(startp, lenp);
    k_compact<<<1, 1024>>>();
    dim3 gg(QLEN, 3);
    k_gather<<<gg, 512>>>(hs, pe, mask, out);
}